// round 16
// baseline (speedup 1.0000x reference)
#include <cuda_runtime.h>
#include <cuda_bf16.h>
#include <cuda_fp16.h>
#include <math.h>
#include <stdint.h>

// Problem constants (fixed shapes per reference)
#define NN 100000
#define FF 128
#define CC 40
#define EE 1600000

// Scratch (device globals — no allocation allowed in kernel_launch)
__device__ float  g_bufA[(size_t)NN * FF];
__device__ __half g_hbuf[(size_t)NN * FF];     // fp16 gather source (x, then layer-1 out)
__device__ int   g_off[NN + 1];
__device__ int   g_cursor[NN];
__device__ int   g_ssrc[EE];
__device__ int   g_idx_is64;
__device__ int   g_bagg[128];
__device__ volatile int g_bflag[128];

// ===========================================================================
// Init: zero CSR offsets + scan flags AND (block 0) sniff edge_index dtype.
// ===========================================================================
__global__ void k_init(const long long* __restrict__ ei, int e, int n) {
    int i = blockIdx.x * blockDim.x + threadIdx.x;
    if (i <= n) g_off[i] = 0;
    if (i < 128) { g_bagg[i] = 0; g_bflag[i] = 0; }
    if (blockIdx.x == 0 && threadIdx.x < 32) {
        int lane = threadIdx.x;
        long long step = e / 32; if (step < 1) step = 1;
        long long j = lane * step;
        int bad = 0;
        if (j < e) {
            long long v = ei[j];
            bad = (v < 0 || v >= n) ? 1 : 0;
        }
        unsigned m = __ballot_sync(0xffffffffu, bad);
        if (lane == 0) g_idx_is64 = (m == 0u) ? 1 : 0;
    }
}

__device__ __forceinline__ int load_idx(const void* ei, long long elem, int is64) {
    return is64 ? (int)((const long long*)ei)[elem] : ((const int*)ei)[elem];
}

// ===========================================================================
// Convert fp32 -> fp16 (for the gather source)
// ===========================================================================
__global__ void k_cvt(const float* __restrict__ in, __half* __restrict__ out,
                      long long nelem) {
    long long i = ((long long)blockIdx.x * blockDim.x + threadIdx.x) * 4;
    if (i >= nelem) return;
    float4 v = *(const float4*)&in[i];
    __half2 h0 = __floats2half2_rn(v.x, v.y);
    __half2 h1 = __floats2half2_rn(v.z, v.w);
    uint2 p;
    p.x = *(uint32_t*)&h0;
    p.y = *(uint32_t*)&h1;
    *(uint2*)&out[i] = p;
}

// ===========================================================================
// CSR construction: histogram -> single-kernel scan -> scatter
// ===========================================================================
__global__ void k_hist(const void* __restrict__ ei, int e, int n) {
    int i = blockIdx.x * blockDim.x + threadIdx.x;
    if (i >= e) return;
    int is64 = g_idx_is64;
    int d = load_idx(ei, (long long)e + i, is64);
    if ((unsigned)d < (unsigned)n) atomicAdd(&g_off[d + 1], 1);
}

__global__ void k_scanF(int n) {
    __shared__ int wsum[32];
    __shared__ int s_prefix;
    int tid = threadIdx.x, lane = tid & 31, wid = tid >> 5;
    int bid = blockIdx.x;
    int gid = bid * 1024 + tid;
    int v = (gid <= n) ? g_off[gid] : 0;
    #pragma unroll
    for (int d = 1; d < 32; d <<= 1) {
        int t = __shfl_up_sync(0xffffffffu, v, d);
        if (lane >= d) v += t;
    }
    if (lane == 31) wsum[wid] = v;
    __syncthreads();
    if (wid == 0) {
        int w = wsum[lane];
        #pragma unroll
        for (int d = 1; d < 32; d <<= 1) {
            int t = __shfl_up_sync(0xffffffffu, w, d);
            if (lane >= d) w += t;
        }
        wsum[lane] = w;
    }
    __syncthreads();
    if (wid > 0) v += wsum[wid - 1];
    if (tid == 0) {
        g_bagg[bid] = wsum[31];
        __threadfence();
        g_bflag[bid] = 1;
    }
    if (wid == 0) {
        int sum = 0;
        for (int p = lane; p < bid; p += 32) {
            while (g_bflag[p] == 0) { }
            sum += *(volatile int*)&g_bagg[p];
        }
        #pragma unroll
        for (int d = 16; d; d >>= 1) sum += __shfl_xor_sync(0xffffffffu, sum, d);
        if (lane == 0) s_prefix = sum;
    }
    __syncthreads();
    int outv = v + s_prefix;
    if (gid <= n) g_off[gid] = outv;
    if (gid < n) g_cursor[gid] = outv;
}

__global__ void k_scatter(const void* __restrict__ ei, int e, int n) {
    int i = blockIdx.x * blockDim.x + threadIdx.x;
    if (i >= e) return;
    int is64 = g_idx_is64;
    int s = load_idx(ei, (long long)i, is64);
    int d = load_idx(ei, (long long)e + i, is64);
    if ((unsigned)d < (unsigned)n && (unsigned)s < (unsigned)n) {
        int pos = atomicAdd(&g_cursor[d], 1);
        if (pos < EE) g_ssrc[pos] = s;
    }
}

// ===========================================================================
// GIN aggregation (fp16 gather, fp32 accumulate) — verified R15 version.
// ===========================================================================
__device__ __forceinline__ float4 h4f(uint2 u) {
    __half2 a = *(__half2*)&u.x;
    __half2 b = *(__half2*)&u.y;
    float2 fa = __half22float2(a), fb = __half22float2(b);
    return make_float4(fa.x, fa.y, fb.x, fb.y);
}

__global__ void k_agg_h(const __half* __restrict__ hin, float* __restrict__ hout,
                        const float* __restrict__ epsp, int n) {
    int g = blockIdx.x * blockDim.x + threadIdx.x;
    int node = g >> 5;
    if (node >= n) return;
    int lane = g & 31;
    float sc = 1.0f + *epsp;
    const uint2* base = (const uint2*)hin;
    float4 acc = h4f(__ldg(&base[(size_t)node * 32 + lane]));
    acc.x *= sc; acc.y *= sc; acc.z *= sc; acc.w *= sc;
    float4 acc2 = make_float4(0.f, 0.f, 0.f, 0.f);
    int beg = g_off[node], end = g_off[node + 1];
    int e = beg;
    for (; e + 3 < end; e += 4) {
        int s0 = g_ssrc[e];
        int s1 = g_ssrc[e + 1];
        int s2 = g_ssrc[e + 2];
        int s3 = g_ssrc[e + 3];
        float4 v0 = h4f(__ldg(&base[(size_t)s0 * 32 + lane]));
        float4 v1 = h4f(__ldg(&base[(size_t)s1 * 32 + lane]));
        float4 v2 = h4f(__ldg(&base[(size_t)s2 * 32 + lane]));
        float4 v3 = h4f(__ldg(&base[(size_t)s3 * 32 + lane]));
        acc.x += v0.x; acc.y += v0.y; acc.z += v0.z; acc.w += v0.w;
        acc2.x += v1.x; acc2.y += v1.y; acc2.z += v1.z; acc2.w += v1.w;
        acc.x += v2.x; acc.y += v2.y; acc.z += v2.z; acc.w += v2.w;
        acc2.x += v3.x; acc2.y += v3.y; acc2.z += v3.z; acc2.w += v3.w;
    }
    for (; e < end; e++) {
        int s = g_ssrc[e];
        float4 v = h4f(__ldg(&base[(size_t)s * 32 + lane]));
        acc.x += v.x; acc.y += v.y; acc.z += v.z; acc.w += v.w;
    }
    acc.x += acc2.x; acc.y += acc2.y; acc.z += acc2.z; acc.w += acc2.w;
    *(float4*)&hout[(size_t)node * FF + lane * 4] = acc;
}

// ===========================================================================
// Shared GEMM helpers
// ===========================================================================
#define STR 136
#define WBYTES (128 * STR * 2)    // one 128-row bf16 plane: 34816 B

__device__ __forceinline__ uint32_t smem_u32(const void* p) {
    uint32_t a;
    asm("{ .reg .u64 t; cvta.to.shared.u64 t, %1; cvt.u32.u64 %0, t; }" : "=r"(a) : "l"(p));
    return a;
}

__device__ __forceinline__ void split2(float x, float y, uint32_t& hi, uint32_t& lo) {
    __nv_bfloat162 h = __floats2bfloat162_rn(x, y);
    float rx = x - __bfloat162float(h.x);
    float ry = y - __bfloat162float(h.y);
    __nv_bfloat162 l = __floats2bfloat162_rn(rx, ry);
    hi = *(uint32_t*)&h;
    lo = *(uint32_t*)&l;
}

__device__ __forceinline__ void mma_bf16(float& c0, float& c1, float& c2, float& c3,
                                         uint32_t a0, uint32_t a1, uint32_t a2, uint32_t a3,
                                         uint32_t b0, uint32_t b1) {
    asm volatile(
        "mma.sync.aligned.m16n8k16.row.col.f32.bf16.bf16.f32 "
        "{%0,%1,%2,%3}, {%4,%5,%6,%7}, {%8,%9}, {%0,%1,%2,%3};"
        : "+f"(c0), "+f"(c1), "+f"(c2), "+f"(c3)
        : "r"(a0), "r"(a1), "r"(a2), "r"(a3), "r"(b0), "r"(b1));
}

__device__ __forceinline__ void ldsm4(uint32_t& r0, uint32_t& r1, uint32_t& r2,
                                      uint32_t& r3, uint32_t addr) {
    asm volatile("ldmatrix.sync.aligned.m8n8.x4.shared.b16 {%0,%1,%2,%3}, [%4];"
                 : "=r"(r0), "=r"(r1), "=r"(r2), "=r"(r3) : "r"(addr));
}

// ===========================================================================
// FUSED Lin1+ReLU+Lin2+ReLU: hbuf(fp16) = relu(relu(in@w1+b1)@w2+b2)
// smem: W1hi/lo, W2hi/lo (128xSTR each), Ahi/Alo (64xSTR, reused for stage 2).
// 1 block/SM, register-pipelined A loads.
// ===========================================================================
#define G12_SMEM (4 * WBYTES + 2 * (64 * STR * 2))   // 174080 B

__global__ void __launch_bounds__(256, 1)
k_gemm12(const float* __restrict__ in,
         const float* __restrict__ w1, const float* __restrict__ b1,
         const float* __restrict__ w2, const float* __restrict__ b2,
         __half* __restrict__ out, int nrows) {
    extern __shared__ __align__(16) uint16_t smu[];
    uint16_t* W1hi = smu;
    uint16_t* W1lo = W1hi + 128 * STR;
    uint16_t* W2hi = W1lo + 128 * STR;
    uint16_t* W2lo = W2hi + 128 * STR;
    uint16_t* Ahi  = W2lo + 128 * STR;           // [64][STR], reused stage 2
    uint16_t* Alo  = Ahi + 64 * STR;
    __shared__ float sb1[128], sb2[128];

    int tid = threadIdx.x, lane = tid & 31, wid = tid >> 5;
    if (tid < 128) { sb1[tid] = b1[tid]; sb2[tid] = b2[tid]; }

    for (int i = tid; i < 8192; i += 256) {
        int n = i & 127;
        int k0 = (i >> 7) * 2;
        uint32_t hi, lo;
        split2(w1[k0 * 128 + n], w1[(k0 + 1) * 128 + n], hi, lo);
        *(uint32_t*)&W1hi[n * STR + k0] = hi;
        *(uint32_t*)&W1lo[n * STR + k0] = lo;
        split2(w2[k0 * 128 + n], w2[(k0 + 1) * 128 + n], hi, lo);
        *(uint32_t*)&W2hi[n * STR + k0] = hi;
        *(uint32_t*)&W2lo[n * STR + k0] = lo;
    }
    __syncthreads();

    int g = lane >> 2, tq = lane & 3;
    int wr = wid & 1, wc = wid >> 1;
    int ntiles = (nrows + 63) / 64;

    int m8 = lane >> 3, rw = lane & 7;
    uint32_t sAhi = smem_u32(Ahi), sAlo = smem_u32(Alo);
    uint32_t sW1hi = smem_u32(W1hi), sW1lo = smem_u32(W1lo);
    uint32_t sW2hi = smem_u32(W2hi), sW2lo = smem_u32(W2lo);
    uint32_t aoff0 = (uint32_t)(((wr * 32 + (m8 & 1) * 8 + rw) * STR + (m8 >> 1) * 8) * 2);
    uint32_t aoff1 = (uint32_t)(((wr * 32 + 16 + (m8 & 1) * 8 + rw) * STR + (m8 >> 1) * 8) * 2);
    uint32_t boff0 = (uint32_t)(((wc * 32 + (m8 >> 1) * 8 + rw) * STR + (m8 & 1) * 8) * 2);
    uint32_t boff1 = (uint32_t)(((wc * 32 + 16 + (m8 >> 1) * 8 + rw) * STR + (m8 & 1) * 8) * 2);

    int t_r[4], t_c0[4];
    #pragma unroll
    for (int it = 0; it < 4; it++) {
        int task = tid + 256 * it;
        t_r[it] = task >> 4;
        t_c0[it] = (task & 15) * 8;
    }

    float4 pa[4], pb[4];
    {
        int row0 = blockIdx.x * 64;
        #pragma unroll
        for (int it = 0; it < 4; it++) {
            int gr = row0 + t_r[it];
            if (gr < nrows) {
                pa[it] = *(const float4*)&in[(size_t)gr * 128 + t_c0[it]];
                pb[it] = *(const float4*)&in[(size_t)gr * 128 + t_c0[it] + 4];
            } else {
                pa[it] = make_float4(0.f, 0.f, 0.f, 0.f);
                pb[it] = make_float4(0.f, 0.f, 0.f, 0.f);
            }
        }
    }

    for (int tile = blockIdx.x; tile < ntiles; tile += gridDim.x) {
        int row0 = tile * 64;
        // stage-1 A: prefetched regs -> smem
        #pragma unroll
        for (int it = 0; it < 4; it++) {
            uint32_t h[4], l[4];
            split2(pa[it].x, pa[it].y, h[0], l[0]);
            split2(pa[it].z, pa[it].w, h[1], l[1]);
            split2(pb[it].x, pb[it].y, h[2], l[2]);
            split2(pb[it].z, pb[it].w, h[3], l[3]);
            *(uint4*)&Ahi[t_r[it] * STR + t_c0[it]] = make_uint4(h[0], h[1], h[2], h[3]);
            *(uint4*)&Alo[t_r[it] * STR + t_c0[it]] = make_uint4(l[0], l[1], l[2], l[3]);
        }
        __syncthreads();

        // prefetch next tile
        int ntile = tile + gridDim.x;
        if (ntile < ntiles) {
            int nrow0 = ntile * 64;
            #pragma unroll
            for (int it = 0; it < 4; it++) {
                int gr = nrow0 + t_r[it];
                if (gr < nrows) {
                    pa[it] = *(const float4*)&in[(size_t)gr * 128 + t_c0[it]];
                    pb[it] = *(const float4*)&in[(size_t)gr * 128 + t_c0[it] + 4];
                } else {
                    pa[it] = make_float4(0.f, 0.f, 0.f, 0.f);
                    pb[it] = make_float4(0.f, 0.f, 0.f, 0.f);
                }
            }
        }

        // ---- stage 1 mainloop (W1) ----
        float acc[2][4][4];
        #pragma unroll
        for (int nt = 0; nt < 4; nt++) {
            float bx = sb1[wc * 32 + nt * 8 + 2 * tq];
            float by = sb1[wc * 32 + nt * 8 + 2 * tq + 1];
            #pragma unroll
            for (int mt = 0; mt < 2; mt++) {
                acc[mt][nt][0] = bx; acc[mt][nt][1] = by;
                acc[mt][nt][2] = bx; acc[mt][nt][3] = by;
            }
        }
        #pragma unroll
        for (int k0 = 0; k0 < 8; k0++) {
            uint32_t kb = (uint32_t)(k0 * 32);
            uint32_t ah[2][4], al[2][4], bh4[2][4], bl4[2][4];
            ldsm4(ah[0][0], ah[0][1], ah[0][2], ah[0][3], sAhi + aoff0 + kb);
            ldsm4(ah[1][0], ah[1][1], ah[1][2], ah[1][3], sAhi + aoff1 + kb);
            ldsm4(al[0][0], al[0][1], al[0][2], al[0][3], sAlo + aoff0 + kb);
            ldsm4(al[1][0], al[1][1], al[1][2], al[1][3], sAlo + aoff1 + kb);
            ldsm4(bh4[0][0], bh4[0][1], bh4[0][2], bh4[0][3], sW1hi + boff0 + kb);
            ldsm4(bh4[1][0], bh4[1][1], bh4[1][2], bh4[1][3], sW1hi + boff1 + kb);
            ldsm4(bl4[0][0], bl4[0][1], bl4[0][2], bl4[0][3], sW1lo + boff0 + kb);
            ldsm4(bl4[1][0], bl4[1][1], bl4[1][2], bl4[1][3], sW1lo + boff1 + kb);
            #pragma unroll
            for (int mt = 0; mt < 2; mt++)
                #pragma unroll
                for (int nt = 0; nt < 4; nt++) {
                    uint32_t b0h = bh4[nt >> 1][(nt & 1) * 2];
                    uint32_t b1h = bh4[nt >> 1][(nt & 1) * 2 + 1];
                    uint32_t b0l = bl4[nt >> 1][(nt & 1) * 2];
                    uint32_t b1l = bl4[nt >> 1][(nt & 1) * 2 + 1];
                    mma_bf16(acc[mt][nt][0], acc[mt][nt][1], acc[mt][nt][2], acc[mt][nt][3],
                             ah[mt][0], ah[mt][1], ah[mt][2], ah[mt][3], b0h, b1h);
                    mma_bf16(acc[mt][nt][0], acc[mt][nt][1], acc[mt][nt][2], acc[mt][nt][3],
                             ah[mt][0], ah[mt][1], ah[mt][2], ah[mt][3], b0l, b1l);
                    mma_bf16(acc[mt][nt][0], acc[mt][nt][1], acc[mt][nt][2], acc[mt][nt][3],
                             al[mt][0], al[mt][1], al[mt][2], al[mt][3], b0h, b1h);
                }
        }
        __syncthreads();   // all warps done reading stage-1 A

        // relu(acc) -> rebuild A in place (bf16 hi/lo)
        #pragma unroll
        for (int mt = 0; mt < 2; mt++) {
            int r0 = wr * 32 + mt * 16 + g;
            #pragma unroll
            for (int nt = 0; nt < 4; nt++) {
                int col = wc * 32 + nt * 8 + 2 * tq;
                float o0 = fmaxf(acc[mt][nt][0], 0.0f);
                float o1 = fmaxf(acc[mt][nt][1], 0.0f);
                float o2 = fmaxf(acc[mt][nt][2], 0.0f);
                float o3 = fmaxf(acc[mt][nt][3], 0.0f);
                uint32_t h, l;
                split2(o0, o1, h, l);
                *(uint32_t*)&Ahi[r0 * STR + col] = h;
                *(uint32_t*)&Alo[r0 * STR + col] = l;
                split2(o2, o3, h, l);
                *(uint32_t*)&Ahi[(r0 + 8) * STR + col] = h;
                *(uint32_t*)&Alo[(r0 + 8) * STR + col] = l;
            }
        }
        __syncthreads();

        // ---- stage 2 mainloop (W2) ----
        #pragma unroll
        for (int nt = 0; nt < 4; nt++) {
            float bx = sb2[wc * 32 + nt * 8 + 2 * tq];
            float by = sb2[wc * 32 + nt * 8 + 2 * tq + 1];
            #pragma unroll
            for (int mt = 0; mt < 2; mt++) {
                acc[mt][nt][0] = bx; acc[mt][nt][1] = by;
                acc[mt][nt][2] = bx; acc[mt][nt][3] = by;
            }
        }
        #pragma unroll
        for (int k0 = 0; k0 < 8; k0++) {
            uint32_t kb = (uint32_t)(k0 * 32);
            uint32_t ah[2][4], al[2][4], bh4[2][4], bl4[2][4];
            ldsm4(ah[0][0], ah[0][1], ah[0][2], ah[0][3], sAhi + aoff0 + kb);
            ldsm4(ah[1][0], ah[1][1], ah[1][2], ah[1][3], sAhi + aoff1 + kb);
            ldsm4(al[0][0], al[0][1], al[0][2], al[0][3], sAlo + aoff0 + kb);
            ldsm4(al[1][0], al[1][1], al[1][2], al[1][3], sAlo + aoff1 + kb);
            ldsm4(bh4[0][0], bh4[0][1], bh4[0][2], bh4[0][3], sW2hi + boff0 + kb);
            ldsm4(bh4[1][0], bh4[1][1], bh4[1][2], bh4[1][3], sW2hi + boff1 + kb);
            ldsm4(bl4[0][0], bl4[0][1], bl4[0][2], bl4[0][3], sW2lo + boff0 + kb);
            ldsm4(bl4[1][0], bl4[1][1], bl4[1][2], bl4[1][3], sW2lo + boff1 + kb);
            #pragma unroll
            for (int mt = 0; mt < 2; mt++)
                #pragma unroll
                for (int nt = 0; nt < 4; nt++) {
                    uint32_t b0h = bh4[nt >> 1][(nt & 1) * 2];
                    uint32_t b1h = bh4[nt >> 1][(nt & 1) * 2 + 1];
                    uint32_t b0l = bl4[nt >> 1][(nt & 1) * 2];
                    uint32_t b1l = bl4[nt >> 1][(nt & 1) * 2 + 1];
                    mma_bf16(acc[mt][nt][0], acc[mt][nt][1], acc[mt][nt][2], acc[mt][nt][3],
                             ah[mt][0], ah[mt][1], ah[mt][2], ah[mt][3], b0h, b1h);
                    mma_bf16(acc[mt][nt][0], acc[mt][nt][1], acc[mt][nt][2], acc[mt][nt][3],
                             ah[mt][0], ah[mt][1], ah[mt][2], ah[mt][3], b0l, b1l);
                    mma_bf16(acc[mt][nt][0], acc[mt][nt][1], acc[mt][nt][2], acc[mt][nt][3],
                             al[mt][0], al[mt][1], al[mt][2], al[mt][3], b0h, b1h);
                }
        }

        // epilogue: relu -> fp16 store
        #pragma unroll
        for (int mt = 0; mt < 2; mt++) {
            int gr0 = row0 + wr * 32 + mt * 16 + g;
            #pragma unroll
            for (int nt = 0; nt < 4; nt++) {
                int col = wc * 32 + nt * 8 + 2 * tq;
                float o0 = fmaxf(acc[mt][nt][0], 0.0f);
                float o1 = fmaxf(acc[mt][nt][1], 0.0f);
                float o2 = fmaxf(acc[mt][nt][2], 0.0f);
                float o3 = fmaxf(acc[mt][nt][3], 0.0f);
                if (gr0 < nrows) {
                    __half2 p = __floats2half2_rn(o0, o1);
                    *(uint32_t*)&out[(size_t)gr0 * 128 + col] = *(uint32_t*)&p;
                }
                if (gr0 + 8 < nrows) {
                    __half2 p = __floats2half2_rn(o2, o3);
                    *(uint32_t*)&out[(size_t)(gr0 + 8) * 128 + col] = *(uint32_t*)&p;
                }
            }
        }
        __syncthreads();
    }
}

// ===========================================================================
// FUSED Lin3+ReLU+Lin4+log_softmax: out = log_softmax(relu(in@w3+b3)@w4+b4)
// smem: W3hi/lo (128xSTR), W4hi/lo (64xSTR), Ahi/Alo (64xSTR, reused), sacc.
// ===========================================================================
#define G3F_SMEM (2 * WBYTES + 2 * (64 * STR * 2) + 2 * (64 * STR * 2) + 64 * 41 * 4 + 256)

__global__ void __launch_bounds__(256, 1)
k_gemm3f(const float* __restrict__ in,
         const float* __restrict__ w3, const float* __restrict__ b3,
         const float* __restrict__ w4, const float* __restrict__ b4,
         float* __restrict__ out, int nrows) {
    extern __shared__ __align__(16) uint16_t smu[];
    uint16_t* W3hi = smu;
    uint16_t* W3lo = W3hi + 128 * STR;
    uint16_t* W4hi = W3lo + 128 * STR;           // [64][STR]
    uint16_t* W4lo = W4hi + 64 * STR;
    uint16_t* Ahi  = W4lo + 64 * STR;            // [64][STR], reused stage 2
    uint16_t* Alo  = Ahi + 64 * STR;
    float* sacc = (float*)(Alo + 64 * STR);      // [64][41]
    float* sb4  = sacc + 64 * 41;                // [64]
    __shared__ float sb3[128];

    int tid = threadIdx.x, lane = tid & 31, wid = tid >> 5;
    if (tid < 128) sb3[tid] = b3[tid];
    if (tid < 64) sb4[tid] = (tid < CC) ? b4[tid] : 0.0f;

    for (int i = tid; i < 8192; i += 256) {
        int n = i & 127;
        int k0 = (i >> 7) * 2;
        uint32_t hi, lo;
        split2(w3[k0 * 128 + n], w3[(k0 + 1) * 128 + n], hi, lo);
        *(uint32_t*)&W3hi[n * STR + k0] = hi;
        *(uint32_t*)&W3lo[n * STR + k0] = lo;
    }
    for (int i = tid; i < 64 * 64; i += 256) {
        int n = i & 63;
        int k0 = (i >> 6) * 2;
        float va = (n < CC) ? w4[k0 * CC + n] : 0.0f;
        float vb = (n < CC) ? w4[(k0 + 1) * CC + n] : 0.0f;
        uint32_t hi, lo;
        split2(va, vb, hi, lo);
        *(uint32_t*)&W4hi[n * STR + k0] = hi;
        *(uint32_t*)&W4lo[n * STR + k0] = lo;
    }
    __syncthreads();

    int g = lane >> 2, tq = lane & 3;
    int wr = wid & 1, wc = wid >> 1;
    int ntiles = (nrows + 63) / 64;

    int m8 = lane >> 3, rw = lane & 7;
    uint32_t sAhi = smem_u32(Ahi), sAlo = smem_u32(Alo);
    uint32_t sW3hi = smem_u32(W3hi), sW3lo = smem_u32(W3lo);
    uint32_t aoff0 = (uint32_t)(((wr * 32 + (m8 & 1) * 8 + rw) * STR + (m8 >> 1) * 8) * 2);
    uint32_t aoff1 = (uint32_t)(((wr * 32 + 16 + (m8 & 1) * 8 + rw) * STR + (m8 >> 1) * 8) * 2);
    uint32_t boff0 = (uint32_t)(((wc * 32 + (m8 >> 1) * 8 + rw) * STR + (m8 & 1) * 8) * 2);
    uint32_t boff1 = (uint32_t)(((wc * 32 + 16 + (m8 >> 1) * 8 + rw) * STR + (m8 & 1) * 8) * 2);

    int t_r[4], t_c0[4];
    #pragma unroll
    for (int it = 0; it < 4; it++) {
        int task = tid + 256 * it;
        t_r[it] = task >> 4;
        t_c0[it] = (task & 15) * 8;
    }

    float4 pa[4], pb[4];
    {
        int row0 = blockIdx.x * 64;
        #pragma unroll
        for (int it = 0; it < 4; it++) {
            int gr = row0 + t_r[it];
            if (gr < nrows) {
                pa[it] = *(const float4*)&in[(size_t)gr * 128 + t_c0[it]];
                pb[it] = *(const float4*)&in[(size_t)gr * 128 + t_c0[it] + 4];
            } else {
                pa[it] = make_float4(0.f, 0.f, 0.f, 0.f);
                pb[it] = make_float4(0.f, 0.f, 0.f, 0.f);
            }
        }
    }

    for (int tile = blockIdx.x; tile < ntiles; tile += gridDim.x) {
        int row0 = tile * 64;
        #pragma unroll
        for (int it = 0; it < 4; it++) {
            uint32_t h[4], l[4];
            split2(pa[it].x, pa[it].y, h[0], l[0]);
            split2(pa[it].z, pa[it].w, h[1], l[1]);
            split2(pb[it].x, pb[it].y, h[2], l[2]);
            split2(pb[it].z, pb[it].w, h[3], l[3]);
            *(uint4*)&Ahi[t_r[it] * STR + t_c0[it]] = make_uint4(h[0], h[1], h[2], h[3]);
            *(uint4*)&Alo[t_r[it] * STR + t_c0[it]] = make_uint4(l[0], l[1], l[2], l[3]);
        }
        __syncthreads();

        int ntile = tile + gridDim.x;
        if (ntile < ntiles) {
            int nrow0 = ntile * 64;
            #pragma unroll
            for (int it = 0; it < 4; it++) {
                int gr = nrow0 + t_r[it];
                if (gr < nrows) {
                    pa[it] = *(const float4*)&in[(size_t)gr * 128 + t_c0[it]];
                    pb[it] = *(const float4*)&in[(size_t)gr * 128 + t_c0[it] + 4];
                } else {
                    pa[it] = make_float4(0.f, 0.f, 0.f, 0.f);
                    pb[it] = make_float4(0.f, 0.f, 0.f, 0.f);
                }
            }
        }

        // ---- stage 1 mainloop (W3) ----
        float acc[2][4][4];
        #pragma unroll
        for (int nt = 0; nt < 4; nt++) {
            float bx = sb3[wc * 32 + nt * 8 + 2 * tq];
            float by = sb3[wc * 32 + nt * 8 + 2 * tq + 1];
            #pragma unroll
            for (int mt = 0; mt < 2; mt++) {
                acc[mt][nt][0] = bx; acc[mt][nt][1] = by;
                acc[mt][nt][2] = bx; acc[mt][nt][3] = by;
            }
        }
        #pragma unroll
        for (int k0 = 0; k0 < 8; k0++) {
            uint32_t kb = (uint32_t)(k0 * 32);
            uint32_t ah[2][4], al[2][4], bh4[2][4], bl4[2][4];
            ldsm4(ah[0][0], ah[0][1], ah[0][2], ah[0][3], sAhi + aoff0 + kb);
            ldsm4(ah[1][0], ah[1][1], ah[1][2], ah[1][3], sAhi + aoff1 + kb);
            ldsm4(al[0][0], al[0][1], al[0][2], al[0][3], sAlo + aoff0 + kb);
            ldsm4(al[1][0], al[1][1], al[1][2], al[1][3], sAlo + aoff1 + kb);
            ldsm4(bh4[0][0], bh4[0][1], bh4[0][2], bh4[0][3], sW3hi + boff0 + kb);
            ldsm4(bh4[1][0], bh4[1][1], bh4[1][2], bh4[1][3], sW3hi + boff1 + kb);
            ldsm4(bl4[0][0], bl4[0][1], bl4[0][2], bl4[0][3], sW3lo + boff0 + kb);
            ldsm4(bl4[1][0], bl4[1][1], bl4[1][2], bl4[1][3], sW3lo + boff1 + kb);
            #pragma unroll
            for (int mt = 0; mt < 2; mt++)
                #pragma unroll
                for (int nt = 0; nt < 4; nt++) {
                    uint32_t b0h = bh4[nt >> 1][(nt & 1) * 2];
                    uint32_t b1h = bh4[nt >> 1][(nt & 1) * 2 + 1];
                    uint32_t b0l = bl4[nt >> 1][(nt & 1) * 2];
                    uint32_t b1l = bl4[nt >> 1][(nt & 1) * 2 + 1];
                    mma_bf16(acc[mt][nt][0], acc[mt][nt][1], acc[mt][nt][2], acc[mt][nt][3],
                             ah[mt][0], ah[mt][1], ah[mt][2], ah[mt][3], b0h, b1h);
                    mma_bf16(acc[mt][nt][0], acc[mt][nt][1], acc[mt][nt][2], acc[mt][nt][3],
                             ah[mt][0], ah[mt][1], ah[mt][2], ah[mt][3], b0l, b1l);
                    mma_bf16(acc[mt][nt][0], acc[mt][nt][1], acc[mt][nt][2], acc[mt][nt][3],
                             al[mt][0], al[mt][1], al[mt][2], al[mt][3], b0h, b1h);
                }
        }
        __syncthreads();

        // relu -> rebuild A in place
        #pragma unroll
        for (int mt = 0; mt < 2; mt++) {
            int r0 = wr * 32 + mt * 16 + g;
            #pragma unroll
            for (int nt = 0; nt < 4; nt++) {
                int col = wc * 32 + nt * 8 + 2 * tq;
                float o0 = fmaxf(acc[mt][nt][0], 0.0f);
                float o1 = fmaxf(acc[mt][nt][1], 0.0f);
                float o2 = fmaxf(acc[mt][nt][2], 0.0f);
                float o3 = fmaxf(acc[mt][nt][3], 0.0f);
                uint32_t h, l;
                split2(o0, o1, h, l);
                *(uint32_t*)&Ahi[r0 * STR + col] = h;
                *(uint32_t*)&Alo[r0 * STR + col] = l;
                split2(o2, o3, h, l);
                *(uint32_t*)&Ahi[(r0 + 8) * STR + col] = h;
                *(uint32_t*)&Alo[(r0 + 8) * STR + col] = l;
            }
        }
        __syncthreads();

        // ---- stage 2: W4 (64 cols), warp tile 32x16 (scalar frag loads) ----
        float a2[2][2][4];
        #pragma unroll
        for (int nt = 0; nt < 2; nt++) {
            float bx = sb4[wc * 16 + nt * 8 + 2 * tq];
            float by = sb4[wc * 16 + nt * 8 + 2 * tq + 1];
            #pragma unroll
            for (int mt = 0; mt < 2; mt++) {
                a2[mt][nt][0] = bx; a2[mt][nt][1] = by;
                a2[mt][nt][2] = bx; a2[mt][nt][3] = by;
            }
        }
        int arow0 = wr * 32 + g;
        int brow  = wc * 16 + g;
        #pragma unroll
        for (int k0 = 0; k0 < 8; k0++) {
            int kk = k0 * 16 + 2 * tq;
            uint32_t ah[2][4], al[2][4], bh[2][2], bl[2][2];
            #pragma unroll
            for (int mt = 0; mt < 2; mt++) {
                int rbase = (arow0 + mt * 16) * STR + kk;
                ah[mt][0] = *(const uint32_t*)&Ahi[rbase];
                ah[mt][1] = *(const uint32_t*)&Ahi[rbase + 8 * STR];
                ah[mt][2] = *(const uint32_t*)&Ahi[rbase + 8];
                ah[mt][3] = *(const uint32_t*)&Ahi[rbase + 8 * STR + 8];
                al[mt][0] = *(const uint32_t*)&Alo[rbase];
                al[mt][1] = *(const uint32_t*)&Alo[rbase + 8 * STR];
                al[mt][2] = *(const uint32_t*)&Alo[rbase + 8];
                al[mt][3] = *(const uint32_t*)&Alo[rbase + 8 * STR + 8];
            }
            #pragma unroll
            for (int nt = 0; nt < 2; nt++) {
                int nbase = (brow + nt * 8) * STR + kk;
                bh[nt][0] = *(const uint32_t*)&W4hi[nbase];
                bh[nt][1] = *(const uint32_t*)&W4hi[nbase + 8];
                bl[nt][0] = *(const uint32_t*)&W4lo[nbase];
                bl[nt][1] = *(const uint32_t*)&W4lo[nbase + 8];
            }
            #pragma unroll
            for (int mt = 0; mt < 2; mt++)
                #pragma unroll
                for (int nt = 0; nt < 2; nt++) {
                    mma_bf16(a2[mt][nt][0], a2[mt][nt][1], a2[mt][nt][2], a2[mt][nt][3],
                             ah[mt][0], ah[mt][1], ah[mt][2], ah[mt][3],
                             bh[nt][0], bh[nt][1]);
                    mma_bf16(a2[mt][nt][0], a2[mt][nt][1], a2[mt][nt][2], a2[mt][nt][3],
                             ah[mt][0], ah[mt][1], ah[mt][2], ah[mt][3],
                             bl[nt][0], bl[nt][1]);
                    mma_bf16(a2[mt][nt][0], a2[mt][nt][1], a2[mt][nt][2], a2[mt][nt][3],
                             al[mt][0], al[mt][1], al[mt][2], al[mt][3],
                             bh[nt][0], bh[nt][1]);
                }
        }

        // a2 -> sacc (only cols < CC; stride 41)
        #pragma unroll
        for (int mt = 0; mt < 2; mt++) {
            int r0 = wr * 32 + mt * 16 + g;
            #pragma unroll
            for (int nt = 0; nt < 2; nt++) {
                int col = wc * 16 + nt * 8 + 2 * tq;
                if (col < CC) {
                    sacc[r0 * 41 + col]       = a2[mt][nt][0];
                    sacc[r0 * 41 + col + 1]   = a2[mt][nt][1];
                    sacc[(r0 + 8) * 41 + col]     = a2[mt][nt][2];
                    sacc[(r0 + 8) * 41 + col + 1] = a2[mt][nt][3];
                }
            }
        }
        __syncthreads();

        // log_softmax
        #pragma unroll
        for (int rr = 0; rr < 8; rr++) {
            int r = wid * 8 + rr;
            int gr = row0 + r;
            float a0 = sacc[r * 41 + lane];
            float a1 = (lane < 8) ? sacc[r * 41 + 32 + lane] : -1e30f;
            float m = fmaxf(a0, a1);
            #pragma unroll
            for (int d = 16; d; d >>= 1) m = fmaxf(m, __shfl_xor_sync(0xffffffffu, m, d));
            float s = expf(a0 - m) + ((lane < 8) ? expf(a1 - m) : 0.0f);
            #pragma unroll
            for (int d = 16; d; d >>= 1) s += __shfl_xor_sync(0xffffffffu, s, d);
            float lse = m + logf(s);
            if (gr < nrows) {
                out[(size_t)gr * CC + lane] = a0 - lse;
                if (lane < 8) out[(size_t)gr * CC + 32 + lane] = a1 - lse;
            }
        }
        __syncthreads();
    }
}

// ===========================================================================
// Launcher
// ===========================================================================
extern "C" void kernel_launch(void* const* d_in, const int* in_sizes, int n_in,
                              void* d_out, int out_size) {
    const float* x    = (const float*)d_in[0];
    const void*  ei   = d_in[1];
    const float* eps1 = (const float*)d_in[2];
    const float* w1   = (const float*)d_in[3];
    const float* b1   = (const float*)d_in[4];
    const float* w2   = (const float*)d_in[5];
    const float* b2   = (const float*)d_in[6];
    const float* eps2 = (const float*)d_in[7];
    const float* w3   = (const float*)d_in[8];
    const float* b3   = (const float*)d_in[9];
    const float* w4   = (const float*)d_in[10];
    const float* b4   = (const float*)d_in[11];
    float*       out  = (float*)d_out;

    int N = in_sizes[0] / FF;
    int E = in_sizes[1] / 2;
    if (N > NN) N = NN;
    if (E > EE) E = EE;

    cudaFuncSetAttribute(k_gemm12, cudaFuncAttributeMaxDynamicSharedMemorySize, G12_SMEM);
    cudaFuncSetAttribute(k_gemm3f, cudaFuncAttributeMaxDynamicSharedMemorySize, G3F_SMEM);

    void *pA = nullptr, *pH = nullptr;
    cudaGetSymbolAddress(&pA, g_bufA);
    cudaGetSymbolAddress(&pH, g_hbuf);
    float*  bufA = (float*)pA;
    __half* hbuf = (__half*)pH;

    int scan_blocks = (N + 1 + 1023) / 1024;   // <= 98
    long long nelem = (long long)N * FF;

    // CSR build + fp16 conversion of x
    k_init<<<(N + 1 + 255) / 256, 256>>>((const long long*)ei, E, N);
    k_cvt<<<(int)((nelem / 4 + 255) / 256), 256>>>(x, hbuf, nelem);
    k_hist<<<(E + 255) / 256, 256>>>(ei, E, N);
    k_scanF<<<scan_blocks, 1024>>>(N);
    k_scatter<<<(E + 255) / 256, 256>>>(ei, E, N);

    // Layer 1: agg(fp16) -> fused Lin1+ReLU+Lin2+ReLU (fp16 out)
    {
        long long tw = (long long)N * 32;
        k_agg_h<<<(int)((tw + 255) / 256), 256>>>(hbuf, bufA, eps1, N);
    }
    k_gemm12<<<148, 256, G12_SMEM>>>(bufA, w1, b1, w2, b2, hbuf, N);

    // Layer 2: agg(fp16) -> fused Lin3+ReLU+Lin4+log_softmax
    {
        long long tw = (long long)N * 32;
        k_agg_h<<<(int)((tw + 255) / 256), 256>>>(hbuf, bufA, eps2, N);
    }
    k_gemm3f<<<148, 256, G3F_SMEM>>>(bufA, w3, b3, w4, b4, out, N);
}

// round 17
// speedup vs baseline: 1.0081x; 1.0081x over previous
#include <cuda_runtime.h>
#include <cuda_bf16.h>
#include <cuda_fp16.h>
#include <math.h>
#include <stdint.h>

// Problem constants (fixed shapes per reference)
#define NN 100000
#define FF 128
#define CC 40
#define EE 1600000

// Scratch (device globals — no allocation allowed in kernel_launch)
__device__ float  g_bufA[(size_t)NN * FF];
__device__ float  g_bufB[(size_t)NN * FF];
__device__ __half g_hbuf[(size_t)NN * FF];     // fp16 gather source (x, then layer-1 out)
__device__ int   g_off[NN + 1];
__device__ int   g_cursor[NN];
__device__ int   g_ssrc[EE];
__device__ int   g_idx_is64;
__device__ int   g_bagg[128];
__device__ volatile int g_bflag[128];

// ===========================================================================
// Init: zero CSR offsets + scan flags, sniff edge_index dtype (block 0),
// AND convert x fp32 -> fp16 into g_hbuf (grid sized for the convert).
// ===========================================================================
__global__ void k_init(const long long* __restrict__ ei, int e, int n,
                       const float* __restrict__ x, __half* __restrict__ hx,
                       long long nelem) {
    int i = blockIdx.x * blockDim.x + threadIdx.x;
    if (i <= n) g_off[i] = 0;
    if (i < 128) { g_bagg[i] = 0; g_bflag[i] = 0; }
    if (blockIdx.x == 0 && threadIdx.x < 32) {
        int lane = threadIdx.x;
        long long step = e / 32; if (step < 1) step = 1;
        long long j = lane * step;
        int bad = 0;
        if (j < e) {
            long long v = ei[j];
            bad = (v < 0 || v >= n) ? 1 : 0;
        }
        unsigned m = __ballot_sync(0xffffffffu, bad);
        if (lane == 0) g_idx_is64 = (m == 0u) ? 1 : 0;
    }
    // fp32 -> fp16 convert (4 elements per thread)
    long long ci = (long long)i * 4;
    if (ci < nelem) {
        float4 v = *(const float4*)&x[ci];
        __half2 h0 = __floats2half2_rn(v.x, v.y);
        __half2 h1 = __floats2half2_rn(v.z, v.w);
        uint2 p;
        p.x = *(uint32_t*)&h0;
        p.y = *(uint32_t*)&h1;
        *(uint2*)&hx[ci] = p;
    }
}

__device__ __forceinline__ int load_idx(const void* ei, long long elem, int is64) {
    return is64 ? (int)((const long long*)ei)[elem] : ((const int*)ei)[elem];
}

// ===========================================================================
// CSR construction: histogram -> single-kernel scan -> scatter
// ===========================================================================
__global__ void k_hist(const void* __restrict__ ei, int e, int n) {
    int i = blockIdx.x * blockDim.x + threadIdx.x;
    if (i >= e) return;
    int is64 = g_idx_is64;
    int d = load_idx(ei, (long long)e + i, is64);
    if ((unsigned)d < (unsigned)n) atomicAdd(&g_off[d + 1], 1);
}

__global__ void k_scanF(int n) {
    __shared__ int wsum[32];
    __shared__ int s_prefix;
    int tid = threadIdx.x, lane = tid & 31, wid = tid >> 5;
    int bid = blockIdx.x;
    int gid = bid * 1024 + tid;
    int v = (gid <= n) ? g_off[gid] : 0;
    #pragma unroll
    for (int d = 1; d < 32; d <<= 1) {
        int t = __shfl_up_sync(0xffffffffu, v, d);
        if (lane >= d) v += t;
    }
    if (lane == 31) wsum[wid] = v;
    __syncthreads();
    if (wid == 0) {
        int w = wsum[lane];
        #pragma unroll
        for (int d = 1; d < 32; d <<= 1) {
            int t = __shfl_up_sync(0xffffffffu, w, d);
            if (lane >= d) w += t;
        }
        wsum[lane] = w;
    }
    __syncthreads();
    if (wid > 0) v += wsum[wid - 1];
    if (tid == 0) {
        g_bagg[bid] = wsum[31];
        __threadfence();
        g_bflag[bid] = 1;
    }
    if (wid == 0) {
        int sum = 0;
        for (int p = lane; p < bid; p += 32) {
            while (g_bflag[p] == 0) { }
            sum += *(volatile int*)&g_bagg[p];
        }
        #pragma unroll
        for (int d = 16; d; d >>= 1) sum += __shfl_xor_sync(0xffffffffu, sum, d);
        if (lane == 0) s_prefix = sum;
    }
    __syncthreads();
    int outv = v + s_prefix;
    if (gid <= n) g_off[gid] = outv;
    if (gid < n) g_cursor[gid] = outv;
}

__global__ void k_scatter(const void* __restrict__ ei, int e, int n) {
    int i = blockIdx.x * blockDim.x + threadIdx.x;
    if (i >= e) return;
    int is64 = g_idx_is64;
    int s = load_idx(ei, (long long)i, is64);
    int d = load_idx(ei, (long long)e + i, is64);
    if ((unsigned)d < (unsigned)n && (unsigned)s < (unsigned)n) {
        int pos = atomicAdd(&g_cursor[d], 1);
        if (pos < EE) g_ssrc[pos] = s;
    }
}

// ===========================================================================
// GIN aggregation (fp16 gather, fp32 accumulate) — verified R15 version.
// ===========================================================================
__device__ __forceinline__ float4 h4f(uint2 u) {
    __half2 a = *(__half2*)&u.x;
    __half2 b = *(__half2*)&u.y;
    float2 fa = __half22float2(a), fb = __half22float2(b);
    return make_float4(fa.x, fa.y, fb.x, fb.y);
}

__global__ void k_agg_h(const __half* __restrict__ hin, float* __restrict__ hout,
                        const float* __restrict__ epsp, int n) {
    int g = blockIdx.x * blockDim.x + threadIdx.x;
    int node = g >> 5;
    if (node >= n) return;
    int lane = g & 31;
    float sc = 1.0f + *epsp;
    const uint2* base = (const uint2*)hin;
    float4 acc = h4f(__ldg(&base[(size_t)node * 32 + lane]));
    acc.x *= sc; acc.y *= sc; acc.z *= sc; acc.w *= sc;
    float4 acc2 = make_float4(0.f, 0.f, 0.f, 0.f);
    int beg = g_off[node], end = g_off[node + 1];
    int e = beg;
    for (; e + 3 < end; e += 4) {
        int s0 = g_ssrc[e];
        int s1 = g_ssrc[e + 1];
        int s2 = g_ssrc[e + 2];
        int s3 = g_ssrc[e + 3];
        float4 v0 = h4f(__ldg(&base[(size_t)s0 * 32 + lane]));
        float4 v1 = h4f(__ldg(&base[(size_t)s1 * 32 + lane]));
        float4 v2 = h4f(__ldg(&base[(size_t)s2 * 32 + lane]));
        float4 v3 = h4f(__ldg(&base[(size_t)s3 * 32 + lane]));
        acc.x += v0.x; acc.y += v0.y; acc.z += v0.z; acc.w += v0.w;
        acc2.x += v1.x; acc2.y += v1.y; acc2.z += v1.z; acc2.w += v1.w;
        acc.x += v2.x; acc.y += v2.y; acc.z += v2.z; acc.w += v2.w;
        acc2.x += v3.x; acc2.y += v3.y; acc2.z += v3.z; acc2.w += v3.w;
    }
    for (; e < end; e++) {
        int s = g_ssrc[e];
        float4 v = h4f(__ldg(&base[(size_t)s * 32 + lane]));
        acc.x += v.x; acc.y += v.y; acc.z += v.z; acc.w += v.w;
    }
    acc.x += acc2.x; acc.y += acc2.y; acc.z += acc2.z; acc.w += acc2.w;
    *(float4*)&hout[(size_t)node * FF + lane * 4] = acc;
}

// ===========================================================================
// Tensor-core GEMM+ReLU via mma.sync (HMMA), bf16 hi/lo split, f32 accum.
// ldmatrix fragment loads + software-pipelined A-tile gmem loads.
// out_half: epilogue writes fp16 (for the agg2 gather source) else fp32.
// (verified R15 version)
// ===========================================================================
#define STR 136
#define GM_SMEM ((128 * STR * 2 * 2) + (64 * STR * 2 * 2))   // 104448 bytes

__device__ __forceinline__ uint32_t smem_u32(const void* p) {
    uint32_t a;
    asm("{ .reg .u64 t; cvta.to.shared.u64 t, %1; cvt.u32.u64 %0, t; }" : "=r"(a) : "l"(p));
    return a;
}

__device__ __forceinline__ void split2(float x, float y, uint32_t& hi, uint32_t& lo) {
    __nv_bfloat162 h = __floats2bfloat162_rn(x, y);
    float rx = x - __bfloat162float(h.x);
    float ry = y - __bfloat162float(h.y);
    __nv_bfloat162 l = __floats2bfloat162_rn(rx, ry);
    hi = *(uint32_t*)&h;
    lo = *(uint32_t*)&l;
}

__device__ __forceinline__ void mma_bf16(float& c0, float& c1, float& c2, float& c3,
                                         uint32_t a0, uint32_t a1, uint32_t a2, uint32_t a3,
                                         uint32_t b0, uint32_t b1) {
    asm volatile(
        "mma.sync.aligned.m16n8k16.row.col.f32.bf16.bf16.f32 "
        "{%0,%1,%2,%3}, {%4,%5,%6,%7}, {%8,%9}, {%0,%1,%2,%3};"
        : "+f"(c0), "+f"(c1), "+f"(c2), "+f"(c3)
        : "r"(a0), "r"(a1), "r"(a2), "r"(a3), "r"(b0), "r"(b1));
}

__device__ __forceinline__ void ldsm4(uint32_t& r0, uint32_t& r1, uint32_t& r2,
                                      uint32_t& r3, uint32_t addr) {
    asm volatile("ldmatrix.sync.aligned.m8n8.x4.shared.b16 {%0,%1,%2,%3}, [%4];"
                 : "=r"(r0), "=r"(r1), "=r"(r2), "=r"(r3) : "r"(addr));
}

__global__ void __launch_bounds__(256, 2)
k_gemm_mma(const float* __restrict__ in, const float* __restrict__ w,
           const float* __restrict__ bias, void* __restrict__ outp,
           int nrows, int out_half) {
    extern __shared__ __align__(16) uint16_t smu[];
    uint16_t* Whi = smu;                         // [128][STR]
    uint16_t* Wlo = Whi + 128 * STR;
    uint16_t* Ahi = Wlo + 128 * STR;             // [64][STR]
    uint16_t* Alo = Ahi + 64 * STR;
    __shared__ float sbias[128];

    int tid = threadIdx.x, lane = tid & 31, wid = tid >> 5;
    if (tid < 128) sbias[tid] = bias[tid];

    for (int i = tid; i < 8192; i += 256) {
        int n = i & 127;
        int k0 = (i >> 7) * 2;
        float va = w[k0 * 128 + n];
        float vb = w[(k0 + 1) * 128 + n];
        uint32_t hi, lo;
        split2(va, vb, hi, lo);
        *(uint32_t*)&Whi[n * STR + k0] = hi;
        *(uint32_t*)&Wlo[n * STR + k0] = lo;
    }
    __syncthreads();

    int g = lane >> 2;
    int tq = lane & 3;
    int wr = wid & 1;
    int wc = wid >> 1;
    int ntiles = (nrows + 63) / 64;

    int m8 = lane >> 3, rw = lane & 7;
    uint32_t sAhi = smem_u32(Ahi), sAlo = smem_u32(Alo);
    uint32_t sWhi = smem_u32(Whi), sWlo = smem_u32(Wlo);
    uint32_t aoff0 = (uint32_t)(((wr * 32 + 0 * 16 + (m8 & 1) * 8 + rw) * STR + (m8 >> 1) * 8) * 2);
    uint32_t aoff1 = (uint32_t)(((wr * 32 + 1 * 16 + (m8 & 1) * 8 + rw) * STR + (m8 >> 1) * 8) * 2);
    uint32_t boff0 = (uint32_t)(((wc * 32 + 0 * 16 + (m8 >> 1) * 8 + rw) * STR + (m8 & 1) * 8) * 2);
    uint32_t boff1 = (uint32_t)(((wc * 32 + 1 * 16 + (m8 >> 1) * 8 + rw) * STR + (m8 & 1) * 8) * 2);

    int t_r[4], t_c0[4];
    #pragma unroll
    for (int it = 0; it < 4; it++) {
        int task = tid + 256 * it;
        t_r[it] = task >> 4;
        t_c0[it] = (task & 15) * 8;
    }

    float4 pa[4], pb[4];

    {
        int row0 = blockIdx.x * 64;
        #pragma unroll
        for (int it = 0; it < 4; it++) {
            int gr = row0 + t_r[it];
            if (gr < nrows) {
                pa[it] = *(const float4*)&in[(size_t)gr * 128 + t_c0[it]];
                pb[it] = *(const float4*)&in[(size_t)gr * 128 + t_c0[it] + 4];
            } else {
                pa[it] = make_float4(0.f, 0.f, 0.f, 0.f);
                pb[it] = make_float4(0.f, 0.f, 0.f, 0.f);
            }
        }
    }

    for (int tile = blockIdx.x; tile < ntiles; tile += gridDim.x) {
        int row0 = tile * 64;
        #pragma unroll
        for (int it = 0; it < 4; it++) {
            uint32_t h[4], l[4];
            split2(pa[it].x, pa[it].y, h[0], l[0]);
            split2(pa[it].z, pa[it].w, h[1], l[1]);
            split2(pb[it].x, pb[it].y, h[2], l[2]);
            split2(pb[it].z, pb[it].w, h[3], l[3]);
            *(uint4*)&Ahi[t_r[it] * STR + t_c0[it]] = make_uint4(h[0], h[1], h[2], h[3]);
            *(uint4*)&Alo[t_r[it] * STR + t_c0[it]] = make_uint4(l[0], l[1], l[2], l[3]);
        }
        __syncthreads();

        int ntile = tile + gridDim.x;
        if (ntile < ntiles) {
            int nrow0 = ntile * 64;
            #pragma unroll
            for (int it = 0; it < 4; it++) {
                int gr = nrow0 + t_r[it];
                if (gr < nrows) {
                    pa[it] = *(const float4*)&in[(size_t)gr * 128 + t_c0[it]];
                    pb[it] = *(const float4*)&in[(size_t)gr * 128 + t_c0[it] + 4];
                } else {
                    pa[it] = make_float4(0.f, 0.f, 0.f, 0.f);
                    pb[it] = make_float4(0.f, 0.f, 0.f, 0.f);
                }
            }
        }

        float acc[2][4][4];
        #pragma unroll
        for (int nt = 0; nt < 4; nt++) {
            float bx = sbias[wc * 32 + nt * 8 + 2 * tq];
            float by = sbias[wc * 32 + nt * 8 + 2 * tq + 1];
            #pragma unroll
            for (int mt = 0; mt < 2; mt++) {
                acc[mt][nt][0] = bx; acc[mt][nt][1] = by;
                acc[mt][nt][2] = bx; acc[mt][nt][3] = by;
            }
        }
        #pragma unroll
        for (int k0 = 0; k0 < 8; k0++) {
            uint32_t kb = (uint32_t)(k0 * 32);
            uint32_t ah[2][4], al[2][4], bh4[2][4], bl4[2][4];
            ldsm4(ah[0][0], ah[0][1], ah[0][2], ah[0][3], sAhi + aoff0 + kb);
            ldsm4(ah[1][0], ah[1][1], ah[1][2], ah[1][3], sAhi + aoff1 + kb);
            ldsm4(al[0][0], al[0][1], al[0][2], al[0][3], sAlo + aoff0 + kb);
            ldsm4(al[1][0], al[1][1], al[1][2], al[1][3], sAlo + aoff1 + kb);
            ldsm4(bh4[0][0], bh4[0][1], bh4[0][2], bh4[0][3], sWhi + boff0 + kb);
            ldsm4(bh4[1][0], bh4[1][1], bh4[1][2], bh4[1][3], sWhi + boff1 + kb);
            ldsm4(bl4[0][0], bl4[0][1], bl4[0][2], bl4[0][3], sWlo + boff0 + kb);
            ldsm4(bl4[1][0], bl4[1][1], bl4[1][2], bl4[1][3], sWlo + boff1 + kb);
            #pragma unroll
            for (int mt = 0; mt < 2; mt++)
                #pragma unroll
                for (int nt = 0; nt < 4; nt++) {
                    uint32_t b0h = bh4[nt >> 1][(nt & 1) * 2];
                    uint32_t b1h = bh4[nt >> 1][(nt & 1) * 2 + 1];
                    uint32_t b0l = bl4[nt >> 1][(nt & 1) * 2];
                    uint32_t b1l = bl4[nt >> 1][(nt & 1) * 2 + 1];
                    mma_bf16(acc[mt][nt][0], acc[mt][nt][1], acc[mt][nt][2], acc[mt][nt][3],
                             ah[mt][0], ah[mt][1], ah[mt][2], ah[mt][3], b0h, b1h);
                    mma_bf16(acc[mt][nt][0], acc[mt][nt][1], acc[mt][nt][2], acc[mt][nt][3],
                             ah[mt][0], ah[mt][1], ah[mt][2], ah[mt][3], b0l, b1l);
                    mma_bf16(acc[mt][nt][0], acc[mt][nt][1], acc[mt][nt][2], acc[mt][nt][3],
                             al[mt][0], al[mt][1], al[mt][2], al[mt][3], b0h, b1h);
                }
        }

        #pragma unroll
        for (int mt = 0; mt < 2; mt++) {
            int gr0 = row0 + wr * 32 + mt * 16 + g;
            #pragma unroll
            for (int nt = 0; nt < 4; nt++) {
                int col = wc * 32 + nt * 8 + 2 * tq;
                float o0 = fmaxf(acc[mt][nt][0], 0.0f);
                float o1 = fmaxf(acc[mt][nt][1], 0.0f);
                float o2 = fmaxf(acc[mt][nt][2], 0.0f);
                float o3 = fmaxf(acc[mt][nt][3], 0.0f);
                if (out_half) {
                    __half* oh = (__half*)outp;
                    if (gr0 < nrows) {
                        __half2 p = __floats2half2_rn(o0, o1);
                        *(uint32_t*)&oh[(size_t)gr0 * 128 + col] = *(uint32_t*)&p;
                    }
                    if (gr0 + 8 < nrows) {
                        __half2 p = __floats2half2_rn(o2, o3);
                        *(uint32_t*)&oh[(size_t)(gr0 + 8) * 128 + col] = *(uint32_t*)&p;
                    }
                } else {
                    float* of = (float*)outp;
                    if (gr0 < nrows)
                        *(float2*)&of[(size_t)gr0 * 128 + col] = make_float2(o0, o1);
                    if (gr0 + 8 < nrows)
                        *(float2*)&of[(size_t)(gr0 + 8) * 128 + col] = make_float2(o2, o3);
                }
            }
        }
        __syncthreads();
    }
}

// ===========================================================================
// Final layer (tensor-core, fused): out = log_softmax(in @ w4 + b4).
// (verified R15 version)
// ===========================================================================
#define FM_SMEM (4 * 64 * STR * 2 + 64 * 41 * 4 + 256)

__global__ void __launch_bounds__(256, 2)
k_final_mma(const float* __restrict__ in, const float* __restrict__ w,
            const float* __restrict__ bias, float* __restrict__ out, int nrows) {
    extern __shared__ __align__(16) uint16_t smu[];
    uint16_t* W4hi = smu;
    uint16_t* W4lo = W4hi + 64 * STR;
    uint16_t* Ahi  = W4lo + 64 * STR;
    uint16_t* Alo  = Ahi + 64 * STR;
    float* sacc = (float*)(Alo + 64 * STR);
    float* sb   = sacc + 64 * 41;

    int tid = threadIdx.x, lane = tid & 31, wid = tid >> 5;
    if (tid < 64) sb[tid] = (tid < CC) ? bias[tid] : 0.0f;

    for (int i = tid; i < 64 * 64; i += 256) {
        int n = i & 63;
        int k0 = (i >> 6) * 2;
        float va = (n < CC) ? w[k0 * CC + n] : 0.0f;
        float vb = (n < CC) ? w[(k0 + 1) * CC + n] : 0.0f;
        uint32_t hi, lo;
        split2(va, vb, hi, lo);
        *(uint32_t*)&W4hi[n * STR + k0] = hi;
        *(uint32_t*)&W4lo[n * STR + k0] = lo;
    }
    __syncthreads();

    int g = lane >> 2;
    int tq = lane & 3;
    int wr = wid & 1;
    int wc = wid >> 1;
    int ntiles = (nrows + 63) / 64;

    for (int tile = blockIdx.x; tile < ntiles; tile += gridDim.x) {
        int row0 = tile * 64;
        #pragma unroll
        for (int it = 0; it < 4; it++) {
            int task = tid + 256 * it;
            int r = task >> 4;
            int c0 = (task & 15) * 8;
            int gr = row0 + r;
            float v[8];
            if (gr < nrows) {
                float4 p0 = *(const float4*)&in[(size_t)gr * 128 + c0];
                float4 p1 = *(const float4*)&in[(size_t)gr * 128 + c0 + 4];
                v[0] = p0.x; v[1] = p0.y; v[2] = p0.z; v[3] = p0.w;
                v[4] = p1.x; v[5] = p1.y; v[6] = p1.z; v[7] = p1.w;
            } else {
                #pragma unroll
                for (int j = 0; j < 8; j++) v[j] = 0.0f;
            }
            uint32_t h[4], l[4];
            split2(v[0], v[1], h[0], l[0]);
            split2(v[2], v[3], h[1], l[1]);
            split2(v[4], v[5], h[2], l[2]);
            split2(v[6], v[7], h[3], l[3]);
            *(uint4*)&Ahi[r * STR + c0] = make_uint4(h[0], h[1], h[2], h[3]);
            *(uint4*)&Alo[r * STR + c0] = make_uint4(l[0], l[1], l[2], l[3]);
        }
        __syncthreads();

        float acc[2][2][4];
        #pragma unroll
        for (int nt = 0; nt < 2; nt++) {
            float bx = sb[wc * 16 + nt * 8 + 2 * tq];
            float by = sb[wc * 16 + nt * 8 + 2 * tq + 1];
            #pragma unroll
            for (int mt = 0; mt < 2; mt++) {
                acc[mt][nt][0] = bx; acc[mt][nt][1] = by;
                acc[mt][nt][2] = bx; acc[mt][nt][3] = by;
            }
        }
        int arow0 = wr * 32 + g;
        int brow  = wc * 16 + g;
        #pragma unroll
        for (int k0 = 0; k0 < 8; k0++) {
            int kk = k0 * 16 + 2 * tq;
            uint32_t ah[2][4], al[2][4], bh[2][2], bl[2][2];
            #pragma unroll
            for (int mt = 0; mt < 2; mt++) {
                int rbase = (arow0 + mt * 16) * STR + kk;
                ah[mt][0] = *(const uint32_t*)&Ahi[rbase];
                ah[mt][1] = *(const uint32_t*)&Ahi[rbase + 8 * STR];
                ah[mt][2] = *(const uint32_t*)&Ahi[rbase + 8];
                ah[mt][3] = *(const uint32_t*)&Ahi[rbase + 8 * STR + 8];
                al[mt][0] = *(const uint32_t*)&Alo[rbase];
                al[mt][1] = *(const uint32_t*)&Alo[rbase + 8 * STR];
                al[mt][2] = *(const uint32_t*)&Alo[rbase + 8];
                al[mt][3] = *(const uint32_t*)&Alo[rbase + 8 * STR + 8];
            }
            #pragma unroll
            for (int nt = 0; nt < 2; nt++) {
                int nbase = (brow + nt * 8) * STR + kk;
                bh[nt][0] = *(const uint32_t*)&W4hi[nbase];
                bh[nt][1] = *(const uint32_t*)&W4hi[nbase + 8];
                bl[nt][0] = *(const uint32_t*)&W4lo[nbase];
                bl[nt][1] = *(const uint32_t*)&W4lo[nbase + 8];
            }
            #pragma unroll
            for (int mt = 0; mt < 2; mt++)
                #pragma unroll
                for (int nt = 0; nt < 2; nt++) {
                    mma_bf16(acc[mt][nt][0], acc[mt][nt][1], acc[mt][nt][2], acc[mt][nt][3],
                             ah[mt][0], ah[mt][1], ah[mt][2], ah[mt][3],
                             bh[nt][0], bh[nt][1]);
                    mma_bf16(acc[mt][nt][0], acc[mt][nt][1], acc[mt][nt][2], acc[mt][nt][3],
                             ah[mt][0], ah[mt][1], ah[mt][2], ah[mt][3],
                             bl[nt][0], bl[nt][1]);
                    mma_bf16(acc[mt][nt][0], acc[mt][nt][1], acc[mt][nt][2], acc[mt][nt][3],
                             al[mt][0], al[mt][1], al[mt][2], al[mt][3],
                             bh[nt][0], bh[nt][1]);
                }
        }

        #pragma unroll
        for (int mt = 0; mt < 2; mt++) {
            int r0 = wr * 32 + mt * 16 + g;
            #pragma unroll
            for (int nt = 0; nt < 2; nt++) {
                int col = wc * 16 + nt * 8 + 2 * tq;
                if (col < CC) {
                    sacc[r0 * 41 + col]       = acc[mt][nt][0];
                    sacc[r0 * 41 + col + 1]   = acc[mt][nt][1];
                    sacc[(r0 + 8) * 41 + col]     = acc[mt][nt][2];
                    sacc[(r0 + 8) * 41 + col + 1] = acc[mt][nt][3];
                }
            }
        }
        __syncthreads();

        #pragma unroll
        for (int rr = 0; rr < 8; rr++) {
            int r = wid * 8 + rr;
            int gr = row0 + r;
            float a0 = sacc[r * 41 + lane];
            float a1 = (lane < 8) ? sacc[r * 41 + 32 + lane] : -1e30f;
            float m = fmaxf(a0, a1);
            #pragma unroll
            for (int d = 16; d; d >>= 1) m = fmaxf(m, __shfl_xor_sync(0xffffffffu, m, d));
            float s = expf(a0 - m) + ((lane < 8) ? expf(a1 - m) : 0.0f);
            #pragma unroll
            for (int d = 16; d; d >>= 1) s += __shfl_xor_sync(0xffffffffu, s, d);
            float lse = m + logf(s);
            if (gr < nrows) {
                out[(size_t)gr * CC + lane] = a0 - lse;
                if (lane < 8) out[(size_t)gr * CC + 32 + lane] = a1 - lse;
            }
        }
        __syncthreads();
    }
}

// ===========================================================================
// Launcher
// ===========================================================================
extern "C" void kernel_launch(void* const* d_in, const int* in_sizes, int n_in,
                              void* d_out, int out_size) {
    const float* x    = (const float*)d_in[0];
    const void*  ei   = d_in[1];
    const float* eps1 = (const float*)d_in[2];
    const float* w1   = (const float*)d_in[3];
    const float* b1   = (const float*)d_in[4];
    const float* w2   = (const float*)d_in[5];
    const float* b2   = (const float*)d_in[6];
    const float* eps2 = (const float*)d_in[7];
    const float* w3   = (const float*)d_in[8];
    const float* b3   = (const float*)d_in[9];
    const float* w4   = (const float*)d_in[10];
    const float* b4   = (const float*)d_in[11];
    float*       out  = (float*)d_out;

    int N = in_sizes[0] / FF;
    int E = in_sizes[1] / 2;
    if (N > NN) N = NN;
    if (E > EE) E = EE;

    cudaFuncSetAttribute(k_gemm_mma, cudaFuncAttributeMaxDynamicSharedMemorySize, GM_SMEM);
    cudaFuncSetAttribute(k_final_mma, cudaFuncAttributeMaxDynamicSharedMemorySize, FM_SMEM);

    void *pA = nullptr, *pB = nullptr, *pH = nullptr;
    cudaGetSymbolAddress(&pA, g_bufA);
    cudaGetSymbolAddress(&pB, g_bufB);
    cudaGetSymbolAddress(&pH, g_hbuf);
    float*  bufA = (float*)pA;
    float*  bufB = (float*)pB;
    __half* hbuf = (__half*)pH;

    int scan_blocks = (N + 1 + 1023) / 1024;   // <= 98
    long long nelem = (long long)N * FF;

    // CSR build; init also zeroes offsets, sniffs dtype, and converts x->fp16
    int init_blocks = (int)((nelem / 4 + 255) / 256);   // covers zero range too
    k_init<<<init_blocks, 256>>>((const long long*)ei, E, N, x, hbuf, nelem);
    k_hist<<<(E + 255) / 256, 256>>>(ei, E, N);
    k_scanF<<<scan_blocks, 1024>>>(N);
    k_scatter<<<(E + 255) / 256, 256>>>(ei, E, N);

    // Layer 1: agg(fp16) -> Lin1+ReLU -> Lin2+ReLU (fp16 out)
    {
        long long tw = (long long)N * 32;
        k_agg_h<<<(int)((tw + 255) / 256), 256>>>(hbuf, bufA, eps1, N);
    }
    k_gemm_mma<<<296, 256, GM_SMEM>>>(bufA, w1, b1, bufB, N, 0);
    k_gemm_mma<<<296, 256, GM_SMEM>>>(bufB, w2, b2, hbuf, N, 1);   // fp16 out

    // Layer 2: agg(fp16) -> Lin3+ReLU -> Lin4+log_softmax
    {
        long long tw = (long long)N * 32;
        k_agg_h<<<(int)((tw + 255) / 256), 256>>>(hbuf, bufA, eps2, N);
    }
    k_gemm_mma<<<296, 256, GM_SMEM>>>(bufA, w3, b3, bufB, N, 0);
    k_final_mma<<<296, 256, FM_SMEM>>>(bufB, w4, b4, out, N);
}